// round 13
// baseline (speedup 1.0000x reference)
#include <cuda_runtime.h>
#include <cuda_fp16.h>
#include <math_constants.h>
#include <cstdint>

#define NN   10000
#define FF   128
#define DEG  32
#define OUTF 128

// ---------------------------------------------------------------------------
// Scratch (__device__ globals; no allocation allowed) — all fp16
// ---------------------------------------------------------------------------
__device__ __half g_Ch[(size_t)NN * 512];    // 0.5 * center projections [i][m*128+f]
__device__ __half g_P [(size_t)NN * 512];    // 0.5 * neighbor projections [j][m*128+f]
__device__ __half g_Xh[(size_t)NN * 128];    // 0.5 * X  (A of gemm_cp AND agg x_j)
__device__ __half g_Wh[(size_t)1024 * 128];  // Wbig transposed [n][k]
__device__ __half g_Ah[(size_t)NN * 512];    // H  [i][512]
__device__ __half g_Bh[(size_t)128 * 512];   // W transposed [n][k]

// ---------------------------------------------------------------------------
// Helpers
// ---------------------------------------------------------------------------
__device__ __forceinline__ uint32_t smem_u32(const void* p) {
    uint32_t a;
    asm("{ .reg .u64 t; cvta.to.shared.u64 t, %1; cvt.u32.u64 %0, t; }" : "=r"(a) : "l"(p));
    return a;
}
__device__ __forceinline__ void ldmatrix_x4(uint32_t* r, uint32_t addr) {
    asm volatile("ldmatrix.sync.aligned.m8n8.x4.shared.b16 {%0,%1,%2,%3}, [%4];"
                 : "=r"(r[0]), "=r"(r[1]), "=r"(r[2]), "=r"(r[3]) : "r"(addr));
}
__device__ __forceinline__ void ldmatrix_x2(uint32_t* r, uint32_t addr) {
    asm volatile("ldmatrix.sync.aligned.m8n8.x2.shared.b16 {%0,%1}, [%2];"
                 : "=r"(r[0]), "=r"(r[1]) : "r"(addr));
}
__device__ __forceinline__ void mma_f16(float* c, const uint32_t* a, const uint32_t* b) {
    asm volatile(
        "mma.sync.aligned.m16n8k16.row.col.f32.f16.f16.f32 "
        "{%0,%1,%2,%3}, {%4,%5,%6,%7}, {%8,%9}, {%0,%1,%2,%3};"
        : "+f"(c[0]), "+f"(c[1]), "+f"(c[2]), "+f"(c[3])
        : "r"(a[0]), "r"(a[1]), "r"(a[2]), "r"(a[3]), "r"(b[0]), "r"(b[1]));
}
__device__ __forceinline__ void cp_async16(uint32_t smaddr, const void* gptr) {
    asm volatile("cp.async.ca.shared.global [%0], [%1], 16;"
                 :: "r"(smaddr), "l"(gptr) : "memory");
}
__device__ __forceinline__ __half2 htanh2(__half2 a) {
    uint32_t av = *reinterpret_cast<uint32_t*>(&a), rv;
    asm("tanh.approx.f16x2 %0, %1;" : "=r"(rv) : "r"(av));
    return *reinterpret_cast<__half2*>(&rv);
}
__device__ __forceinline__ uint32_t h2u(__half2 h) { return *reinterpret_cast<uint32_t*>(&h); }

// ===========================================================================
// Kernel 0: prep — Xh = 0.5*X fp16; Wh = Wbig^T fp16; Bh = W^T fp16
// ===========================================================================
__global__ __launch_bounds__(256) void prep_kernel(
    const float* __restrict__ X,
    const float* __restrict__ Wsum, const float* __restrict__ Wmean,
    const float* __restrict__ Wmax, const float* __restrict__ Wmin,
    const float* __restrict__ W)
{
    const int tid = blockIdx.x * blockDim.x + threadIdx.x;
    const int stride = gridDim.x * blockDim.x;

    const float4* X4 = (const float4*)X;
    for (int v = tid; v < NN * 128 / 4; v += stride) {
        float4 f = X4[v];
        __half2 h0 = __floats2half2_rn(0.5f * f.x, 0.5f * f.y);
        __half2 h1 = __floats2half2_rn(0.5f * f.z, 0.5f * f.w);
        uint2 ph; ph.x = h2u(h0); ph.y = h2u(h1);
        *(uint2*)&g_Xh[(size_t)v * 4] = ph;
    }

    for (int v = tid; v < 1024 * 32; v += stride) {
        int n  = v >> 5;
        int k4 = (v & 31) * 4;
        int m  = (n >> 7) & 3;
        const float* __restrict__ Wm = (m == 0) ? Wsum : (m == 1) ? Wmean : (m == 2) ? Wmax : Wmin;
        int rowOff = (n >= 512) ? 128 : 0;
        int f = n & 127;
        float a0 = Wm[(rowOff + k4 + 0) * 128 + f];
        float a1 = Wm[(rowOff + k4 + 1) * 128 + f];
        float a2 = Wm[(rowOff + k4 + 2) * 128 + f];
        float a3 = Wm[(rowOff + k4 + 3) * 128 + f];
        uint2 pk;
        pk.x = h2u(__floats2half2_rn(a0, a1));
        pk.y = h2u(__floats2half2_rn(a2, a3));
        *(uint2*)&g_Wh[(size_t)n * 128 + k4] = pk;
    }

    // Bh[n][k] = W[k][n], fp16
    for (int v = tid; v < 128 * 128; v += stride) {
        int n = v & 127;
        int k4 = (v >> 7) * 4;
        uint2 pk;
        pk.x = h2u(__floats2half2_rn(W[(size_t)(k4 + 0) * 128 + n],
                                     W[(size_t)(k4 + 1) * 128 + n]));
        pk.y = h2u(__floats2half2_rn(W[(size_t)(k4 + 2) * 128 + n],
                                     W[(size_t)(k4 + 3) * 128 + n]));
        *(uint2*)&g_Bh[(size_t)n * 512 + k4] = pk;
    }
}

// ===========================================================================
// Kernel 1: CP = (0.5X) @ Wh^T via fp16 mma (M=10000, N=1024, K=128)
// CTA covers M=128 x N=256 as two 128-wide N-tiles: A loaded once, B0 in
// group 0, B1 in group 1 (streams in during tile-0 compute).
// 8 warps (4m x 2n), warp tile 32x64 per N-tile.
// ===========================================================================
#define CP_STRIDE 136
#define CP_TILEB  (128 * CP_STRIDE * 2)     // 34816 per matrix tile
#define CP_SMEM   (3 * CP_TILEB)            // A + B0 + B1 = 104448

__global__ __launch_bounds__(256) void gemm_cp_mma_kernel()
{
    extern __shared__ char smem[];
    const uint32_t sA  = smem_u32(smem);
    const uint32_t sB0 = sA + CP_TILEB;
    const uint32_t sB1 = sA + 2 * CP_TILEB;

    const int tid  = threadIdx.x;
    const int lane = tid & 31;
    const int wid  = tid >> 5;
    const int warpM = wid >> 1;
    const int warpN = wid & 1;

    const int nBase0  = blockIdx.x * 256;
    const int rowBase = blockIdx.y * 128;

    // Group 0: A + B0
    for (int v = tid; v < 2048; v += 256) {
        int r = v >> 4, q = v & 15;
        int grow = rowBase + r;
        if (grow >= NN) grow = 0;   // rows >= NN discarded in epilogue
        cp_async16(sA + (r * CP_STRIDE + q * 8) * 2,
                   &g_Xh[(size_t)grow * 128 + q * 8]);
    }
    for (int v = tid; v < 2048; v += 256) {
        int n = v >> 4, q = v & 15;
        cp_async16(sB0 + (n * CP_STRIDE + q * 8) * 2,
                   &g_Wh[(size_t)(nBase0 + n) * 128 + q * 8]);
    }
    asm volatile("cp.async.commit_group;" ::: "memory");
    // Group 1: B1
    for (int v = tid; v < 2048; v += 256) {
        int n = v >> 4, q = v & 15;
        cp_async16(sB1 + (n * CP_STRIDE + q * 8) * 2,
                   &g_Wh[(size_t)(nBase0 + 128 + n) * 128 + q * 8]);
    }
    asm volatile("cp.async.commit_group;" ::: "memory");

    float acc[2][8][4];

    auto compute_and_store = [&](uint32_t bS, int nTileBase) {
#pragma unroll
        for (int mt = 0; mt < 2; mt++)
#pragma unroll
            for (int nt = 0; nt < 8; nt++)
#pragma unroll
                for (int e = 0; e < 4; e++) acc[mt][nt][e] = 0.f;

#pragma unroll
        for (int kb = 0; kb < 128; kb += 16) {
            uint32_t aF[2][4];
#pragma unroll
            for (int mt = 0; mt < 2; mt++) {
                int row = warpM * 32 + mt * 16 + (lane & 15);
                int col = kb + (lane >> 4) * 8;
                ldmatrix_x4(aF[mt], sA + (row * CP_STRIDE + col) * 2);
            }
            uint32_t bF[8][2];
#pragma unroll
            for (int nt = 0; nt < 8; nt++) {
                int nrow = warpN * 64 + nt * 8 + (lane & 7);
                int col  = kb + ((lane & 15) >> 3) * 8;
                ldmatrix_x2(bF[nt], bS + (nrow * CP_STRIDE + col) * 2);
            }
#pragma unroll
            for (int mt = 0; mt < 2; mt++)
#pragma unroll
                for (int nt = 0; nt < 8; nt++)
                    mma_f16(acc[mt][nt], aF[mt], bF[nt]);
        }

        // Epilogue: acc == 0.5*X@W (A pre-halved); store fp16
#pragma unroll
        for (int mt = 0; mt < 2; mt++) {
            const int r0 = rowBase + warpM * 32 + mt * 16 + (lane >> 2);
            const int r1 = r0 + 8;
#pragma unroll
            for (int nt = 0; nt < 8; nt++) {
                const int cLoc = warpN * 64 + nt * 8 + (lane & 3) * 2;
                const int cAbs = nTileBase + cLoc;
                __half* dstBase = (cAbs < 512) ? g_Ch : g_P;
                const int cOut = cAbs & 511;
                if (r0 < NN) {
                    __half2 h = __floats2half2_rn(acc[mt][nt][0], acc[mt][nt][1]);
                    *(uint32_t*)&dstBase[(size_t)r0 * 512 + cOut] = h2u(h);
                }
                if (r1 < NN) {
                    __half2 h = __floats2half2_rn(acc[mt][nt][2], acc[mt][nt][3]);
                    *(uint32_t*)&dstBase[(size_t)r1 * 512 + cOut] = h2u(h);
                }
            }
        }
    };

    asm volatile("cp.async.wait_group 1;" ::: "memory");
    __syncthreads();
    compute_and_store(sB0, nBase0);

    asm volatile("cp.async.wait_group 0;" ::: "memory");
    __syncthreads();
    compute_and_store(sB1, nBase0 + 128);
}

// ===========================================================================
// Kernel 2: per-node aggregation (half2 pipeline) -> g_Ah fp16 H
// mask*x = fma(tanh.f16x2(c+p), hx, hx); c,p,hx all pre-halved fp16.
// ===========================================================================
__device__ __forceinline__ float4 add4(float4 a, float4 b) {
    return make_float4(a.x + b.x, a.y + b.y, a.z + b.z, a.w + b.w);
}
__device__ __forceinline__ void ld_h2pair(const __half* p, __half2& a, __half2& b) {
    uint2 v = *(const uint2*)p;
    a = *reinterpret_cast<__half2*>(&v.x);
    b = *reinterpret_cast<__half2*>(&v.y);
}
__device__ __forceinline__ void st_h4(__half* dst, float4 v) {
    uint2 pk;
    pk.x = h2u(__floats2half2_rn(v.x, v.y));
    pk.y = h2u(__floats2half2_rn(v.z, v.w));
    *(uint2*)dst = pk;
}

__global__ __launch_bounds__(128) void agg_kernel(
    const float* __restrict__ x, const int* __restrict__ nbr)
{
    const int warp = threadIdx.x >> 5;
    const int lane = threadIdx.x & 31;
    const int i = blockIdx.x * 4 + warp;
    if (i >= NN) return;

    const int jl = nbr[i * DEG + lane];
    const float4* __restrict__ x4 = (const float4*)x;

    const float4 xi = x4[i * 32 + lane];

    __half2 c0a, c0b, c1a, c1b, c2a, c2b, c3a, c3b;
    {
        const __half* crow = &g_Ch[(size_t)i * 512 + lane * 4];
        ld_h2pair(crow + 0,   c0a, c0b);
        ld_h2pair(crow + 128, c1a, c1b);
        ld_h2pair(crow + 256, c2a, c2b);
        ld_h2pair(crow + 384, c3a, c3b);
    }

    float4 s0 = make_float4(0.f, 0.f, 0.f, 0.f);
    float4 s1 = make_float4(0.f, 0.f, 0.f, 0.f);
    const uint32_t NINF2 = 0xFC00FC00u, PINF2 = 0x7C007C00u;
    __half2 s2a = *reinterpret_cast<const __half2*>(&NINF2);
    __half2 s2b = s2a;
    __half2 s3a = *reinterpret_cast<const __half2*>(&PINF2);
    __half2 s3b = s3a;

#pragma unroll 8
    for (int d = 0; d < DEG; d++) {
        const int j = __shfl_sync(0xffffffffu, jl, d);

        __half2 hxa, hxb;
        ld_h2pair(&g_Xh[(size_t)j * 128 + lane * 4], hxa, hxb);

        const __half* prow = &g_P[(size_t)j * 512 + lane * 4];
        __half2 p0a, p0b, p1a, p1b, p2a, p2b, p3a, p3b;
        ld_h2pair(prow + 0,   p0a, p0b);
        ld_h2pair(prow + 128, p1a, p1b);
        ld_h2pair(prow + 256, p2a, p2b);
        ld_h2pair(prow + 384, p3a, p3b);

        {
            __half2 m = __hfma2(htanh2(__hadd2(c0a, p0a)), hxa, hxa);
            float2 f = __half22float2(m); s0.x += f.x; s0.y += f.y;
            m = __hfma2(htanh2(__hadd2(c0b, p0b)), hxb, hxb);
            f = __half22float2(m); s0.z += f.x; s0.w += f.y;
        }
        {
            __half2 m = __hfma2(htanh2(__hadd2(c1a, p1a)), hxa, hxa);
            float2 f = __half22float2(m); s1.x += f.x; s1.y += f.y;
            m = __hfma2(htanh2(__hadd2(c1b, p1b)), hxb, hxb);
            f = __half22float2(m); s1.z += f.x; s1.w += f.y;
        }
        {
            s2a = __hmax2(s2a, __hfma2(htanh2(__hadd2(c2a, p2a)), hxa, hxa));
            s2b = __hmax2(s2b, __hfma2(htanh2(__hadd2(c2b, p2b)), hxb, hxb));
        }
        {
            s3a = __hmin2(s3a, __hfma2(htanh2(__hadd2(c3a, p3a)), hxa, hxa));
            s3b = __hmin2(s3b, __hfma2(htanh2(__hadd2(c3b, p3b)), hxb, hxb));
        }
    }

    const float inv_deg = 1.0f / (float)DEG;
    float4 h0 = add4(xi, s0);
    float4 h1 = add4(xi, make_float4(s1.x * inv_deg, s1.y * inv_deg,
                                     s1.z * inv_deg, s1.w * inv_deg));
    float2 f2a = __half22float2(s2a), f2b = __half22float2(s2b);
    float2 f3a = __half22float2(s3a), f3b = __half22float2(s3b);
    float4 h2 = add4(xi, make_float4(f2a.x, f2a.y, f2b.x, f2b.y));
    float4 h3 = add4(xi, make_float4(f3a.x, f3a.y, f3b.x, f3b.y));

    __half* ah = &g_Ah[(size_t)i * 512];
    st_h4(ah + 0   + lane * 4, h0);
    st_h4(ah + 128 + lane * 4, h1);
    st_h4(ah + 256 + lane * 4, h2);
    st_h4(ah + 384 + lane * 4, h3);
}

// ===========================================================================
// Kernel 3: out = relu(Ah @ Bh^T + bias)  (M=10000, N=128, K=512, fp16 HMMA)
// R9-optimal config: tile M=80 x N=64, grid (125,2), 128 threads,
// 2-stage cp.async, BK=128, warp tile 80x16 (mt=5, nt=2). NKB=4.
// ===========================================================================
#define OUT_NKB    4
#define OUT_AST    136
#define OUT_ABYTES (80 * OUT_AST * 2)
#define OUT_BBYTES (64 * OUT_AST * 2)
#define OUT_STAGE  (OUT_ABYTES + OUT_BBYTES)
#define OUT_SMEM   (2 * OUT_STAGE)

__global__ __launch_bounds__(128) void gemm_out_f16_kernel(
    const float* __restrict__ bias, float* __restrict__ out)
{
    extern __shared__ char smem[];
    const uint32_t sbase = smem_u32(smem);
    const int tid  = threadIdx.x;
    const int lane = tid & 31;
    const int wid  = tid >> 5;
    const int rowBase   = blockIdx.x * 80;   // 125*80 = 10000 exact
    const int nTileBase = blockIdx.y * 64;
    const int nbase     = wid * 16;

    float acc[5][2][4];
#pragma unroll
    for (int mt = 0; mt < 5; mt++)
#pragma unroll
        for (int nt = 0; nt < 2; nt++)
#pragma unroll
            for (int e = 0; e < 4; e++) acc[mt][nt][e] = 0.f;

    auto issue = [&](int kb, int s) {
        const uint32_t abase = sbase + s * OUT_STAGE;
        for (int v = tid; v < 1280; v += 128) {
            int r = v >> 4, q = v & 15;
            cp_async16(abase + (r * OUT_AST + q * 8) * 2,
                       &g_Ah[(size_t)(rowBase + r) * 512 + kb * 128 + q * 8]);
        }
        const uint32_t bbase = abase + OUT_ABYTES;
        for (int v = tid; v < 1024; v += 128) {
            int n = v >> 4, q = v & 15;
            cp_async16(bbase + (n * OUT_AST + q * 8) * 2,
                       &g_Bh[(size_t)(nTileBase + n) * 512 + kb * 128 + q * 8]);
        }
        asm volatile("cp.async.commit_group;" ::: "memory");
    };

    issue(0, 0);

#pragma unroll
    for (int kb = 0; kb < OUT_NKB; kb++) {
        if (kb + 1 < OUT_NKB) {
            issue(kb + 1, (kb + 1) & 1);
            asm volatile("cp.async.wait_group 1;" ::: "memory");
        } else {
            asm volatile("cp.async.wait_group 0;" ::: "memory");
        }
        __syncthreads();

        const uint32_t aS = sbase + (kb & 1) * OUT_STAGE;
        const uint32_t bS = aS + OUT_ABYTES;

#pragma unroll
        for (int ks = 0; ks < 8; ks++) {
            const int col = ks * 16;
            uint32_t aF[5][4];
#pragma unroll
            for (int mt = 0; mt < 5; mt++) {
                int row = mt * 16 + (lane & 15);
                ldmatrix_x4(aF[mt], aS + (row * OUT_AST + col + (lane >> 4) * 8) * 2);
            }
            uint32_t bF[2][2];
#pragma unroll
            for (int nt = 0; nt < 2; nt++) {
                int nrow = nbase + nt * 8 + (lane & 7);
                ldmatrix_x2(bF[nt], bS + (nrow * OUT_AST + col + ((lane & 15) >> 3) * 8) * 2);
            }
#pragma unroll
            for (int mt = 0; mt < 5; mt++)
#pragma unroll
                for (int nt = 0; nt < 2; nt++)
                    mma_f16(acc[mt][nt], aF[mt], bF[nt]);
        }
        __syncthreads();
    }

    // Epilogue: bias + relu
#pragma unroll
    for (int mt = 0; mt < 5; mt++) {
        const int r0 = rowBase + mt * 16 + (lane >> 2);
        const int r1 = r0 + 8;
#pragma unroll
        for (int nt = 0; nt < 2; nt++) {
            const int c = nTileBase + nbase + nt * 8 + (lane & 3) * 2;
            const float b0 = bias[c], b1 = bias[c + 1];
            *(float2*)&out[(size_t)r0 * 128 + c] = make_float2(
                fmaxf(acc[mt][nt][0] + b0, 0.f), fmaxf(acc[mt][nt][1] + b1, 0.f));
            *(float2*)&out[(size_t)r1 * 128 + c] = make_float2(
                fmaxf(acc[mt][nt][2] + b0, 0.f), fmaxf(acc[mt][nt][3] + b1, 0.f));
        }
    }
}

// ===========================================================================
extern "C" void kernel_launch(void* const* d_in, const int* in_sizes, int n_in,
                              void* d_out, int out_size)
{
    const float* x     = (const float*)d_in[0];
    const int*   nbr   = (const int*)  d_in[1];
    const float* Wsum  = (const float*)d_in[2];
    const float* Wmean = (const float*)d_in[3];
    const float* Wmax  = (const float*)d_in[4];
    const float* Wmin  = (const float*)d_in[5];
    const float* W     = (const float*)d_in[6];
    const float* bias  = (const float*)d_in[7];
    float* out = (float*)d_out;

    cudaFuncSetAttribute(gemm_cp_mma_kernel,
                         cudaFuncAttributeMaxDynamicSharedMemorySize, CP_SMEM);
    cudaFuncSetAttribute(gemm_out_f16_kernel,
                         cudaFuncAttributeMaxDynamicSharedMemorySize, OUT_SMEM);

    // 0) fp16 conversions / transposes
    prep_kernel<<<296, 256>>>(x, Wsum, Wmean, Wmax, Wmin, W);

    // 1) CP = (0.5X) @ Wh^T (10000 x 1024), fp16 HMMA, 2 N-tiles per CTA
    {
        dim3 grid(4, (NN + 127) / 128);
        gemm_cp_mma_kernel<<<grid, 256, CP_SMEM>>>();
    }

    // 2) per-node aggregation (half2 pipeline) -> fp16 H
    {
        dim3 grid((NN + 3) / 4);
        agg_kernel<<<grid, 128>>>(x, nbr);
    }

    // 3) out = relu(H @ W + bias), fp16 HMMA, K=512
    {
        dim3 grid(125, 2);
        gemm_out_f16_kernel<<<grid, 128, OUT_SMEM>>>(bias, out);
    }
}

// round 14
// speedup vs baseline: 1.0310x; 1.0310x over previous
#include <cuda_runtime.h>
#include <cuda_fp16.h>
#include <math_constants.h>
#include <cstdint>

#define NN   10000
#define FF   128
#define DEG  32
#define OUTF 128

// ---------------------------------------------------------------------------
// Scratch (__device__ globals; no allocation allowed) — all fp16
// ---------------------------------------------------------------------------
__device__ __half g_Ch[(size_t)NN * 512];    // 0.5 * center projections [i][m*128+f]
__device__ __half g_P [(size_t)NN * 512];    // 0.5 * neighbor projections [j][m*128+f]
__device__ __half g_Xh[(size_t)NN * 128];    // 0.5 * X  (A of gemm_cp AND agg x_j)
__device__ __half g_Wh[(size_t)1024 * 128];  // Wbig transposed [n][k]
__device__ __half g_Ah[(size_t)NN * 512];    // H  [i][512]
__device__ __half g_Bh[(size_t)128 * 512];   // W transposed [n][k]

// ---------------------------------------------------------------------------
// Helpers
// ---------------------------------------------------------------------------
__device__ __forceinline__ uint32_t smem_u32(const void* p) {
    uint32_t a;
    asm("{ .reg .u64 t; cvta.to.shared.u64 t, %1; cvt.u32.u64 %0, t; }" : "=r"(a) : "l"(p));
    return a;
}
__device__ __forceinline__ void ldmatrix_x4(uint32_t* r, uint32_t addr) {
    asm volatile("ldmatrix.sync.aligned.m8n8.x4.shared.b16 {%0,%1,%2,%3}, [%4];"
                 : "=r"(r[0]), "=r"(r[1]), "=r"(r[2]), "=r"(r[3]) : "r"(addr));
}
__device__ __forceinline__ void ldmatrix_x2(uint32_t* r, uint32_t addr) {
    asm volatile("ldmatrix.sync.aligned.m8n8.x2.shared.b16 {%0,%1}, [%2];"
                 : "=r"(r[0]), "=r"(r[1]) : "r"(addr));
}
__device__ __forceinline__ void mma_f16(float* c, const uint32_t* a, const uint32_t* b) {
    asm volatile(
        "mma.sync.aligned.m16n8k16.row.col.f32.f16.f16.f32 "
        "{%0,%1,%2,%3}, {%4,%5,%6,%7}, {%8,%9}, {%0,%1,%2,%3};"
        : "+f"(c[0]), "+f"(c[1]), "+f"(c[2]), "+f"(c[3])
        : "r"(a[0]), "r"(a[1]), "r"(a[2]), "r"(a[3]), "r"(b[0]), "r"(b[1]));
}
__device__ __forceinline__ void cp_async16(uint32_t smaddr, const void* gptr) {
    asm volatile("cp.async.ca.shared.global [%0], [%1], 16;"
                 :: "r"(smaddr), "l"(gptr) : "memory");
}
__device__ __forceinline__ __half2 htanh2(__half2 a) {
    uint32_t av = *reinterpret_cast<uint32_t*>(&a), rv;
    asm("tanh.approx.f16x2 %0, %1;" : "=r"(rv) : "r"(av));
    return *reinterpret_cast<__half2*>(&rv);
}
__device__ __forceinline__ uint32_t h2u(__half2 h) { return *reinterpret_cast<uint32_t*>(&h); }

// ===========================================================================
// Kernel 0: prep — Xh = 0.5*X fp16; Wh = Wbig^T fp16; Bh = W^T fp16
// ===========================================================================
__global__ __launch_bounds__(256) void prep_kernel(
    const float* __restrict__ X,
    const float* __restrict__ Wsum, const float* __restrict__ Wmean,
    const float* __restrict__ Wmax, const float* __restrict__ Wmin,
    const float* __restrict__ W)
{
    const int tid = blockIdx.x * blockDim.x + threadIdx.x;
    const int stride = gridDim.x * blockDim.x;

    const float4* X4 = (const float4*)X;
    for (int v = tid; v < NN * 128 / 4; v += stride) {
        float4 f = X4[v];
        __half2 h0 = __floats2half2_rn(0.5f * f.x, 0.5f * f.y);
        __half2 h1 = __floats2half2_rn(0.5f * f.z, 0.5f * f.w);
        uint2 ph; ph.x = h2u(h0); ph.y = h2u(h1);
        *(uint2*)&g_Xh[(size_t)v * 4] = ph;
    }

    for (int v = tid; v < 1024 * 32; v += stride) {
        int n  = v >> 5;
        int k4 = (v & 31) * 4;
        int m  = (n >> 7) & 3;
        const float* __restrict__ Wm = (m == 0) ? Wsum : (m == 1) ? Wmean : (m == 2) ? Wmax : Wmin;
        int rowOff = (n >= 512) ? 128 : 0;
        int f = n & 127;
        float a0 = Wm[(rowOff + k4 + 0) * 128 + f];
        float a1 = Wm[(rowOff + k4 + 1) * 128 + f];
        float a2 = Wm[(rowOff + k4 + 2) * 128 + f];
        float a3 = Wm[(rowOff + k4 + 3) * 128 + f];
        uint2 pk;
        pk.x = h2u(__floats2half2_rn(a0, a1));
        pk.y = h2u(__floats2half2_rn(a2, a3));
        *(uint2*)&g_Wh[(size_t)n * 128 + k4] = pk;
    }

    // Bh[n][k] = W[k][n], fp16
    for (int v = tid; v < 128 * 128; v += stride) {
        int n = v & 127;
        int k4 = (v >> 7) * 4;
        uint2 pk;
        pk.x = h2u(__floats2half2_rn(W[(size_t)(k4 + 0) * 128 + n],
                                     W[(size_t)(k4 + 1) * 128 + n]));
        pk.y = h2u(__floats2half2_rn(W[(size_t)(k4 + 2) * 128 + n],
                                     W[(size_t)(k4 + 3) * 128 + n]));
        *(uint2*)&g_Bh[(size_t)n * 512 + k4] = pk;
    }
}

// ===========================================================================
// Kernel 1: CP = (0.5X) @ Wh^T via fp16 mma (M=10000, N=1024, K=128)
// R12 config: CTA tile 128x128; 8 warps (4m x 2n), warp tile 32x64.
// Two commit groups (K-halves). A pre-halved -> acc == 0.5 * X@W.
// ===========================================================================
#define CP_STRIDE 136
#define CP_SMEM   (2 * 128 * CP_STRIDE * 2)   // 69,632

__global__ __launch_bounds__(256) void gemm_cp_mma_kernel()
{
    extern __shared__ char smem[];
    __half* Xs = (__half*)smem;
    __half* Ws = (__half*)(smem + 128 * CP_STRIDE * 2);

    const int tid  = threadIdx.x;
    const int lane = tid & 31;
    const int wid  = tid >> 5;
    const int warpM = wid >> 1;
    const int warpN = wid & 1;

    const int nBase   = blockIdx.x * 128;
    const int rowBase = blockIdx.y * 128;

    const uint32_t sXsB = smem_u32(Xs);
    const uint32_t sWsB = smem_u32(Ws);

#pragma unroll
    for (int h = 0; h < 2; h++) {
        for (int v = tid; v < 1024; v += 256) {
            int r = v >> 3, q = (v & 7) + h * 8;
            int grow = rowBase + r;
            if (grow >= NN) grow = 0;   // rows >= NN discarded in epilogue
            cp_async16(sXsB + (r * CP_STRIDE + q * 8) * 2,
                       &g_Xh[(size_t)grow * 128 + q * 8]);
        }
        for (int v = tid; v < 1024; v += 256) {
            int n = v >> 3, q = (v & 7) + h * 8;
            cp_async16(sWsB + (n * CP_STRIDE + q * 8) * 2,
                       &g_Wh[(size_t)(nBase + n) * 128 + q * 8]);
        }
        asm volatile("cp.async.commit_group;" ::: "memory");
    }

    float acc[2][8][4];
#pragma unroll
    for (int mt = 0; mt < 2; mt++)
#pragma unroll
        for (int nt = 0; nt < 8; nt++)
#pragma unroll
            for (int e = 0; e < 4; e++) acc[mt][nt][e] = 0.f;

    asm volatile("cp.async.wait_group 1;" ::: "memory");
    __syncthreads();

#pragma unroll
    for (int half = 0; half < 2; half++) {
        if (half == 1) {
            asm volatile("cp.async.wait_group 0;" ::: "memory");
            __syncthreads();
        }
#pragma unroll
        for (int kk = 0; kk < 64; kk += 16) {
            const int kb = half * 64 + kk;
            uint32_t aF[2][4];
#pragma unroll
            for (int mt = 0; mt < 2; mt++) {
                int row = warpM * 32 + mt * 16 + (lane & 15);
                int col = kb + (lane >> 4) * 8;
                ldmatrix_x4(aF[mt], sXsB + (row * CP_STRIDE + col) * 2);
            }
            uint32_t bF[8][2];
#pragma unroll
            for (int nt = 0; nt < 8; nt++) {
                int nrow = warpN * 64 + nt * 8 + (lane & 7);
                int col  = kb + ((lane & 15) >> 3) * 8;
                ldmatrix_x2(bF[nt], sWsB + (nrow * CP_STRIDE + col) * 2);
            }
#pragma unroll
            for (int mt = 0; mt < 2; mt++)
#pragma unroll
                for (int nt = 0; nt < 8; nt++)
                    mma_f16(acc[mt][nt], aF[mt], bF[nt]);
        }
    }

    // Epilogue: acc is already 0.5*X@W; store fp16 (coalesced)
#pragma unroll
    for (int mt = 0; mt < 2; mt++) {
        const int r0 = rowBase + warpM * 32 + mt * 16 + (lane >> 2);
        const int r1 = r0 + 8;
#pragma unroll
        for (int nt = 0; nt < 8; nt++) {
            const int cLoc = warpN * 64 + nt * 8 + (lane & 3) * 2;
            const int cAbs = nBase + cLoc;
            __half* dstBase = (cAbs < 512) ? g_Ch : g_P;
            const int cOut = cAbs & 511;
            if (r0 < NN) {
                __half2 h = __floats2half2_rn(acc[mt][nt][0], acc[mt][nt][1]);
                *(uint32_t*)&dstBase[(size_t)r0 * 512 + cOut] = h2u(h);
            }
            if (r1 < NN) {
                __half2 h = __floats2half2_rn(acc[mt][nt][2], acc[mt][nt][3]);
                *(uint32_t*)&dstBase[(size_t)r1 * 512 + cOut] = h2u(h);
            }
        }
    }
}

// ===========================================================================
// Kernel 2: per-node aggregation (half2 pipeline, software-prefetched)
// mask*x = fma(tanh.f16x2(c+p), hx, hx); c,p,hx all pre-halved fp16.
// Iteration d+1's 5 global loads are issued before iteration d's math.
// ===========================================================================
__device__ __forceinline__ float4 add4(float4 a, float4 b) {
    return make_float4(a.x + b.x, a.y + b.y, a.z + b.z, a.w + b.w);
}
__device__ __forceinline__ void ld_h2pair(const __half* p, __half2& a, __half2& b) {
    uint2 v = *(const uint2*)p;
    a = *reinterpret_cast<__half2*>(&v.x);
    b = *reinterpret_cast<__half2*>(&v.y);
}
__device__ __forceinline__ void st_h4(__half* dst, float4 v) {
    uint2 pk;
    pk.x = h2u(__floats2half2_rn(v.x, v.y));
    pk.y = h2u(__floats2half2_rn(v.z, v.w));
    *(uint2*)dst = pk;
}

__global__ __launch_bounds__(128) void agg_kernel(
    const float* __restrict__ x, const int* __restrict__ nbr)
{
    const int warp = threadIdx.x >> 5;
    const int lane = threadIdx.x & 31;
    const int i = blockIdx.x * 4 + warp;
    if (i >= NN) return;

    const int jl = nbr[i * DEG + lane];
    const float4* __restrict__ x4 = (const float4*)x;

    const float4 xi = x4[i * 32 + lane];

    __half2 c0a, c0b, c1a, c1b, c2a, c2b, c3a, c3b;
    {
        const __half* crow = &g_Ch[(size_t)i * 512 + lane * 4];
        ld_h2pair(crow + 0,   c0a, c0b);
        ld_h2pair(crow + 128, c1a, c1b);
        ld_h2pair(crow + 256, c2a, c2b);
        ld_h2pair(crow + 384, c3a, c3b);
    }

    float4 s0 = make_float4(0.f, 0.f, 0.f, 0.f);
    float4 s1 = make_float4(0.f, 0.f, 0.f, 0.f);
    const uint32_t NINF2 = 0xFC00FC00u, PINF2 = 0x7C007C00u;
    __half2 s2a = *reinterpret_cast<const __half2*>(&NINF2);
    __half2 s2b = s2a;
    __half2 s3a = *reinterpret_cast<const __half2*>(&PINF2);
    __half2 s3b = s3a;

    // Prefetch iteration 0
    __half2 hxa, hxb, p0a, p0b, p1a, p1b, p2a, p2b, p3a, p3b;
    {
        const int j0 = __shfl_sync(0xffffffffu, jl, 0);
        ld_h2pair(&g_Xh[(size_t)j0 * 128 + lane * 4], hxa, hxb);
        const __half* prow = &g_P[(size_t)j0 * 512 + lane * 4];
        ld_h2pair(prow + 0,   p0a, p0b);
        ld_h2pair(prow + 128, p1a, p1b);
        ld_h2pair(prow + 256, p2a, p2b);
        ld_h2pair(prow + 384, p3a, p3b);
    }

#pragma unroll 4
    for (int d = 0; d < DEG; d++) {
        // Prefetch iteration d+1 while computing d
        __half2 nhxa, nhxb, n0a, n0b, n1a, n1b, n2a, n2b, n3a, n3b;
        if (d + 1 < DEG) {
            const int jn = __shfl_sync(0xffffffffu, jl, d + 1);
            ld_h2pair(&g_Xh[(size_t)jn * 128 + lane * 4], nhxa, nhxb);
            const __half* prow = &g_P[(size_t)jn * 512 + lane * 4];
            ld_h2pair(prow + 0,   n0a, n0b);
            ld_h2pair(prow + 128, n1a, n1b);
            ld_h2pair(prow + 256, n2a, n2b);
            ld_h2pair(prow + 384, n3a, n3b);
        }

        {
            __half2 m = __hfma2(htanh2(__hadd2(c0a, p0a)), hxa, hxa);
            float2 f = __half22float2(m); s0.x += f.x; s0.y += f.y;
            m = __hfma2(htanh2(__hadd2(c0b, p0b)), hxb, hxb);
            f = __half22float2(m); s0.z += f.x; s0.w += f.y;
        }
        {
            __half2 m = __hfma2(htanh2(__hadd2(c1a, p1a)), hxa, hxa);
            float2 f = __half22float2(m); s1.x += f.x; s1.y += f.y;
            m = __hfma2(htanh2(__hadd2(c1b, p1b)), hxb, hxb);
            f = __half22float2(m); s1.z += f.x; s1.w += f.y;
        }
        {
            s2a = __hmax2(s2a, __hfma2(htanh2(__hadd2(c2a, p2a)), hxa, hxa));
            s2b = __hmax2(s2b, __hfma2(htanh2(__hadd2(c2b, p2b)), hxb, hxb));
        }
        {
            s3a = __hmin2(s3a, __hfma2(htanh2(__hadd2(c3a, p3a)), hxa, hxa));
            s3b = __hmin2(s3b, __hfma2(htanh2(__hadd2(c3b, p3b)), hxb, hxb));
        }

        if (d + 1 < DEG) {
            hxa = nhxa; hxb = nhxb;
            p0a = n0a; p0b = n0b; p1a = n1a; p1b = n1b;
            p2a = n2a; p2b = n2b; p3a = n3a; p3b = n3b;
        }
    }

    const float inv_deg = 1.0f / (float)DEG;
    float4 h0 = add4(xi, s0);
    float4 h1 = add4(xi, make_float4(s1.x * inv_deg, s1.y * inv_deg,
                                     s1.z * inv_deg, s1.w * inv_deg));
    float2 f2a = __half22float2(s2a), f2b = __half22float2(s2b);
    float2 f3a = __half22float2(s3a), f3b = __half22float2(s3b);
    float4 h2 = add4(xi, make_float4(f2a.x, f2a.y, f2b.x, f2b.y));
    float4 h3 = add4(xi, make_float4(f3a.x, f3a.y, f3b.x, f3b.y));

    __half* ah = &g_Ah[(size_t)i * 512];
    st_h4(ah + 0   + lane * 4, h0);
    st_h4(ah + 128 + lane * 4, h1);
    st_h4(ah + 256 + lane * 4, h2);
    st_h4(ah + 384 + lane * 4, h3);
}

// ===========================================================================
// Kernel 3: out = relu(Ah @ Bh^T + bias)  (M=10000, N=128, K=512, fp16 HMMA)
// R9-optimal config: tile M=80 x N=64, grid (125,2), 128 threads,
// 2-stage cp.async, BK=128, warp tile 80x16 (mt=5, nt=2). NKB=4.
// ===========================================================================
#define OUT_NKB    4
#define OUT_AST    136
#define OUT_ABYTES (80 * OUT_AST * 2)
#define OUT_BBYTES (64 * OUT_AST * 2)
#define OUT_STAGE  (OUT_ABYTES + OUT_BBYTES)
#define OUT_SMEM   (2 * OUT_STAGE)

__global__ __launch_bounds__(128) void gemm_out_f16_kernel(
    const float* __restrict__ bias, float* __restrict__ out)
{
    extern __shared__ char smem[];
    const uint32_t sbase = smem_u32(smem);
    const int tid  = threadIdx.x;
    const int lane = tid & 31;
    const int wid  = tid >> 5;
    const int rowBase   = blockIdx.x * 80;   // 125*80 = 10000 exact
    const int nTileBase = blockIdx.y * 64;
    const int nbase     = wid * 16;

    float acc[5][2][4];
#pragma unroll
    for (int mt = 0; mt < 5; mt++)
#pragma unroll
        for (int nt = 0; nt < 2; nt++)
#pragma unroll
            for (int e = 0; e < 4; e++) acc[mt][nt][e] = 0.f;

    auto issue = [&](int kb, int s) {
        const uint32_t abase = sbase + s * OUT_STAGE;
        for (int v = tid; v < 1280; v += 128) {
            int r = v >> 4, q = v & 15;
            cp_async16(abase + (r * OUT_AST + q * 8) * 2,
                       &g_Ah[(size_t)(rowBase + r) * 512 + kb * 128 + q * 8]);
        }
        const uint32_t bbase = abase + OUT_ABYTES;
        for (int v = tid; v < 1024; v += 128) {
            int n = v >> 4, q = v & 15;
            cp_async16(bbase + (n * OUT_AST + q * 8) * 2,
                       &g_Bh[(size_t)(nTileBase + n) * 512 + kb * 128 + q * 8]);
        }
        asm volatile("cp.async.commit_group;" ::: "memory");
    };

    issue(0, 0);

#pragma unroll
    for (int kb = 0; kb < OUT_NKB; kb++) {
        if (kb + 1 < OUT_NKB) {
            issue(kb + 1, (kb + 1) & 1);
            asm volatile("cp.async.wait_group 1;" ::: "memory");
        } else {
            asm volatile("cp.async.wait_group 0;" ::: "memory");
        }
        __syncthreads();

        const uint32_t aS = sbase + (kb & 1) * OUT_STAGE;
        const uint32_t bS = aS + OUT_ABYTES;

#pragma unroll
        for (int ks = 0; ks < 8; ks++) {
            const int col = ks * 16;
            uint32_t aF[5][4];
#pragma unroll
            for (int mt = 0; mt < 5; mt++) {
                int row = mt * 16 + (lane & 15);
                ldmatrix_x4(aF[mt], aS + (row * OUT_AST + col + (lane >> 4) * 8) * 2);
            }
            uint32_t bF[2][2];
#pragma unroll
            for (int nt = 0; nt < 2; nt++) {
                int nrow = nbase + nt * 8 + (lane & 7);
                ldmatrix_x2(bF[nt], bS + (nrow * OUT_AST + col + ((lane & 15) >> 3) * 8) * 2);
            }
#pragma unroll
            for (int mt = 0; mt < 5; mt++)
#pragma unroll
                for (int nt = 0; nt < 2; nt++)
                    mma_f16(acc[mt][nt], aF[mt], bF[nt]);
        }
        __syncthreads();
    }

    // Epilogue: bias + relu
#pragma unroll
    for (int mt = 0; mt < 5; mt++) {
        const int r0 = rowBase + mt * 16 + (lane >> 2);
        const int r1 = r0 + 8;
#pragma unroll
        for (int nt = 0; nt < 2; nt++) {
            const int c = nTileBase + nbase + nt * 8 + (lane & 3) * 2;
            const float b0 = bias[c], b1 = bias[c + 1];
            *(float2*)&out[(size_t)r0 * 128 + c] = make_float2(
                fmaxf(acc[mt][nt][0] + b0, 0.f), fmaxf(acc[mt][nt][1] + b1, 0.f));
            *(float2*)&out[(size_t)r1 * 128 + c] = make_float2(
                fmaxf(acc[mt][nt][2] + b0, 0.f), fmaxf(acc[mt][nt][3] + b1, 0.f));
        }
    }
}

// ===========================================================================
extern "C" void kernel_launch(void* const* d_in, const int* in_sizes, int n_in,
                              void* d_out, int out_size)
{
    const float* x     = (const float*)d_in[0];
    const int*   nbr   = (const int*)  d_in[1];
    const float* Wsum  = (const float*)d_in[2];
    const float* Wmean = (const float*)d_in[3];
    const float* Wmax  = (const float*)d_in[4];
    const float* Wmin  = (const float*)d_in[5];
    const float* W     = (const float*)d_in[6];
    const float* bias  = (const float*)d_in[7];
    float* out = (float*)d_out;

    cudaFuncSetAttribute(gemm_cp_mma_kernel,
                         cudaFuncAttributeMaxDynamicSharedMemorySize, CP_SMEM);
    cudaFuncSetAttribute(gemm_out_f16_kernel,
                         cudaFuncAttributeMaxDynamicSharedMemorySize, OUT_SMEM);

    // 0) fp16 conversions / transposes
    prep_kernel<<<296, 256>>>(x, Wsum, Wmean, Wmax, Wmin, W);

    // 1) CP = (0.5X) @ Wh^T (10000 x 1024), fp16 HMMA (R12 config)
    {
        dim3 grid(1024 / 128, (NN + 127) / 128);
        gemm_cp_mma_kernel<<<grid, 256, CP_SMEM>>>();
    }

    // 2) per-node aggregation (half2 pipeline, prefetched) -> fp16 H
    {
        dim3 grid((NN + 3) / 4);
        agg_kernel<<<grid, 128>>>(x, nbr);
    }

    // 3) out = relu(H @ W + bias), fp16 HMMA, K=512
    {
        dim3 grid(125, 2);
        gemm_out_f16_kernel<<<grid, 128, OUT_SMEM>>>(bias, out);
    }
}